// round 3
// baseline (speedup 1.0000x reference)
#include <cuda_runtime.h>
#include <cuda_bf16.h>
#include <math_constants.h>

#define NN 50000
#define EE 800000
#define FDIM 256        // layer-1 feature dim (4 heads * 64)
#define F2DIM 40        // layer-2 feature dim (1 head * 40)
#define NEG_SLOPE 0.2f

// ---------------- scratch (static device globals; no runtime allocation) ----
__device__ __align__(16) float g_feat1[NN * FDIM];   // x @ W1 ; front reused for feat2
__device__ __align__(16) float g_h2[NN * FDIM];      // elu(layer-1 out), flattened
__device__ int g_colidx[EE];                         // CSR: src ids grouped by dst
__device__ int g_counts[NN];
__device__ int g_rowptr[NN + 1];
__device__ int g_cursor[NN];
// feat2[N,40] aliases g_feat1 (feat1 is dead once agg1 has produced g_h2)
#define G_FEAT2 g_feat1

// ---------------- CSR build ------------------------------------------------
__global__ void zero_counts_kernel() {
    int i = blockIdx.x * blockDim.x + threadIdx.x;
    if (i < NN) g_counts[i] = 0;
}

__global__ void hist_kernel(const int* __restrict__ dst) {
    int e = blockIdx.x * blockDim.x + threadIdx.x;
    if (e < EE) atomicAdd(&g_counts[dst[e]], 1);
}

// single-block exclusive scan of g_counts -> g_rowptr / g_cursor
__global__ void scan_kernel() {
    __shared__ int sh[1024];
    __shared__ int carry;
    int tid = threadIdx.x;
    if (tid == 0) carry = 0;
    __syncthreads();
    for (int base = 0; base < NN; base += 1024) {
        int i = base + tid;
        int v = (i < NN) ? g_counts[i] : 0;
        sh[tid] = v;
        __syncthreads();
        #pragma unroll
        for (int off = 1; off < 1024; off <<= 1) {
            int t = (tid >= off) ? sh[tid - off] : 0;
            __syncthreads();
            sh[tid] += t;
            __syncthreads();
        }
        int excl = carry + sh[tid] - v;
        if (i < NN) { g_rowptr[i] = excl; g_cursor[i] = excl; }
        __syncthreads();
        if (tid == 0) carry += sh[1023];
        __syncthreads();
    }
    if (threadIdx.x == 0) g_rowptr[NN] = carry;
}

__global__ void fill_kernel(const int* __restrict__ src, const int* __restrict__ dst) {
    int e = blockIdx.x * blockDim.x + threadIdx.x;
    if (e < EE) {
        int p = atomicAdd(&g_cursor[dst[e]], 1);
        g_colidx[p] = src[e];
    }
}

// ---------------- GEMM1: feat1[N,256] = x[N,256] @ W1[256,256] --------------
// 128x128 block tile, BK=8, 8x8 per-thread register tile, 256 threads.
__global__ __launch_bounds__(256) void gemm1_kernel(const float* __restrict__ A,
                                                    const float* __restrict__ B) {
    __shared__ float As[8][132];   // transposed A tile (k, m), padded
    __shared__ float Bs[8][132];   // (k, n), padded
    int tid = threadIdx.x;
    int tx = tid & 15, ty = tid >> 4;
    int row0 = blockIdx.x * 128;
    int col0 = blockIdx.y * 128;

    float acc[8][8];
    #pragma unroll
    for (int i = 0; i < 8; i++)
        #pragma unroll
        for (int j = 0; j < 8; j++) acc[i][j] = 0.f;

    int am = tid >> 1;              // 0..127
    int ak = (tid & 1) * 4;         // 0 or 4
    int br = tid >> 5;              // 0..7
    int bc = (tid & 31) * 4;        // 0..124

    for (int k0 = 0; k0 < FDIM; k0 += 8) {
        int ar = row0 + am;
        float4 av = make_float4(0.f, 0.f, 0.f, 0.f);
        if (ar < NN) av = *(const float4*)&A[(size_t)ar * FDIM + k0 + ak];
        As[ak + 0][am] = av.x;
        As[ak + 1][am] = av.y;
        As[ak + 2][am] = av.z;
        As[ak + 3][am] = av.w;
        float4 bv = *(const float4*)&B[(k0 + br) * 256 + col0 + bc];
        *(float4*)&Bs[br][bc] = bv;
        __syncthreads();

        #pragma unroll
        for (int k = 0; k < 8; k++) {
            float4 a0 = *(const float4*)&As[k][ty * 8];
            float4 a1 = *(const float4*)&As[k][ty * 8 + 4];
            float4 b0 = *(const float4*)&Bs[k][tx * 8];
            float4 b1 = *(const float4*)&Bs[k][tx * 8 + 4];
            float ar8[8] = {a0.x, a0.y, a0.z, a0.w, a1.x, a1.y, a1.z, a1.w};
            float bc8[8] = {b0.x, b0.y, b0.z, b0.w, b1.x, b1.y, b1.z, b1.w};
            #pragma unroll
            for (int i = 0; i < 8; i++)
                #pragma unroll
                for (int j = 0; j < 8; j++) acc[i][j] += ar8[i] * bc8[j];
        }
        __syncthreads();
    }

    #pragma unroll
    for (int i = 0; i < 8; i++) {
        int r = row0 + ty * 8 + i;
        if (r < NN) {
            float* crow = &g_feat1[(size_t)r * FDIM + col0 + tx * 8];
            *(float4*)&crow[0] = make_float4(acc[i][0], acc[i][1], acc[i][2], acc[i][3]);
            *(float4*)&crow[4] = make_float4(acc[i][4], acc[i][5], acc[i][6], acc[i][7]);
        }
    }
}

// ---------------- layer-1 fused edge-softmax + aggregate --------------------
// one warp per destination node, online softmax, no atomics.
// Grid is sized so every warp maps to a valid node (NN*32 threads exactly).
__device__ __forceinline__ float4 leaky4(float4 v) {
    float4 r;
    r.x = v.x > 0.f ? v.x : NEG_SLOPE * v.x;
    r.y = v.y > 0.f ? v.y : NEG_SLOPE * v.y;
    r.z = v.z > 0.f ? v.z : NEG_SLOPE * v.z;
    r.w = v.w > 0.f ? v.w : NEG_SLOPE * v.w;
    return r;
}
__device__ __forceinline__ float eluf(float x) { return x > 0.f ? x : expm1f(x); }

__global__ __launch_bounds__(256) void agg1_kernel(const float* __restrict__ attn) {
    int w = (blockIdx.x * blockDim.x + threadIdx.x) >> 5;   // always < NN by grid construction
    int lane = threadIdx.x & 31;

    const float4* feat = (const float4*)g_feat1;   // 64 float4 per row
    const float4* at4  = (const float4*)attn;      // 64 float4

    // lane l holds dims of head (l>>4) via float4 l, and head 2+(l>>4) via float4 32+l
    float4 aA = at4[lane];
    float4 aB = at4[32 + lane];
    float4 fd0 = feat[(size_t)w * 64 + lane];
    float4 fd1 = feat[(size_t)w * 64 + 32 + lane];

    int beg = g_rowptr[w], end = g_rowptr[w + 1];
    float mA = -CUDART_INF_F, mB = -CUDART_INF_F, dA = 0.f, dB = 0.f;
    float4 acc0 = make_float4(0.f, 0.f, 0.f, 0.f);
    float4 acc1 = make_float4(0.f, 0.f, 0.f, 0.f);

    for (int k = beg; k < end; k++) {
        int s = g_colidx[k];
        float4 v0 = feat[(size_t)s * 64 + lane];
        float4 v1 = feat[(size_t)s * 64 + 32 + lane];
        float4 e0 = leaky4(make_float4(v0.x + fd0.x, v0.y + fd0.y, v0.z + fd0.z, v0.w + fd0.w));
        float4 e1 = leaky4(make_float4(v1.x + fd1.x, v1.y + fd1.y, v1.z + fd1.z, v1.w + fd1.w));
        float p0 = e0.x * aA.x + e0.y * aA.y + e0.z * aA.z + e0.w * aA.w;
        float p1 = e1.x * aB.x + e1.y * aB.y + e1.z * aB.z + e1.w * aB.w;
        // reduce within 16-lane halves (each half owns one head per score)
        #pragma unroll
        for (int off = 8; off > 0; off >>= 1) {
            p0 += __shfl_xor_sync(0xffffffffu, p0, off);
            p1 += __shfl_xor_sync(0xffffffffu, p1, off);
        }
        // online softmax, head A
        float nmA = fmaxf(mA, p0);
        float scA = __expf(mA - nmA);
        float exA = __expf(p0 - nmA);
        dA = dA * scA + exA;
        acc0.x = acc0.x * scA + exA * v0.x;
        acc0.y = acc0.y * scA + exA * v0.y;
        acc0.z = acc0.z * scA + exA * v0.z;
        acc0.w = acc0.w * scA + exA * v0.w;
        mA = nmA;
        // head B
        float nmB = fmaxf(mB, p1);
        float scB = __expf(mB - nmB);
        float exB = __expf(p1 - nmB);
        dB = dB * scB + exB;
        acc1.x = acc1.x * scB + exB * v1.x;
        acc1.y = acc1.y * scB + exB * v1.y;
        acc1.z = acc1.z * scB + exB * v1.z;
        acc1.w = acc1.w * scB + exB * v1.w;
        mB = nmB;
    }

    float iA = dA > 0.f ? 1.f / dA : 0.f;
    float iB = dB > 0.f ? 1.f / dB : 0.f;
    float4 o0 = make_float4(eluf(acc0.x * iA), eluf(acc0.y * iA), eluf(acc0.z * iA), eluf(acc0.w * iA));
    float4 o1 = make_float4(eluf(acc1.x * iB), eluf(acc1.y * iB), eluf(acc1.z * iB), eluf(acc1.w * iB));
    float4* out = (float4*)g_h2;
    out[(size_t)w * 64 + lane] = o0;
    out[(size_t)w * 64 + 32 + lane] = o1;
}

// ---------------- GEMM2: feat2[N,40] = h2[N,256] @ W2[256,40] ---------------
__global__ __launch_bounds__(256) void gemm2_kernel(const float* __restrict__ W2) {
    __shared__ float hs[4][256];
    int n0 = blockIdx.x * 4;
    int tid = threadIdx.y * 64 + threadIdx.x;
    for (int i = tid; i < 1024; i += 256) {
        int r = n0 + (i >> 8);
        hs[i >> 8][i & 255] = (r < NN) ? g_h2[(size_t)r * 256 + (i & 255)] : 0.f;
    }
    __syncthreads();
    int c = threadIdx.x;
    int r = n0 + threadIdx.y;
    if (c < F2DIM && r < NN) {
        float s = 0.f;
        #pragma unroll 8
        for (int k = 0; k < 256; k++) s += hs[threadIdx.y][k] * W2[k * F2DIM + c];
        G_FEAT2[(size_t)r * F2DIM + c] = s;
    }
}

// ---------------- layer-2 fused edge-softmax + aggregate --------------------
__global__ __launch_bounds__(256) void agg2_kernel(const float* __restrict__ attn2,
                                                   float* __restrict__ out) {
    int w = (blockIdx.x * blockDim.x + threadIdx.x) >> 5;   // always < NN by grid construction
    int lane = threadIdx.x & 31;

    bool hi = lane < 8;
    float a_lo = attn2[lane];
    float a_hi = hi ? attn2[32 + lane] : 0.f;
    float fd_lo = G_FEAT2[(size_t)w * F2DIM + lane];
    float fd_hi = hi ? G_FEAT2[(size_t)w * F2DIM + 32 + lane] : 0.f;

    int beg = g_rowptr[w], end = g_rowptr[w + 1];
    float m = -CUDART_INF_F, d = 0.f, acc_lo = 0.f, acc_hi = 0.f;

    for (int k = beg; k < end; k++) {
        int s = g_colidx[k];
        float v_lo = G_FEAT2[(size_t)s * F2DIM + lane];
        float v_hi = hi ? G_FEAT2[(size_t)s * F2DIM + 32 + lane] : 0.f;
        float e_lo = v_lo + fd_lo; e_lo = e_lo > 0.f ? e_lo : NEG_SLOPE * e_lo;
        float e_hi = v_hi + fd_hi; e_hi = e_hi > 0.f ? e_hi : NEG_SLOPE * e_hi;
        float p = e_lo * a_lo + e_hi * a_hi;
        #pragma unroll
        for (int off = 16; off > 0; off >>= 1) p += __shfl_xor_sync(0xffffffffu, p, off);
        float nm = fmaxf(m, p);
        float sc = __expf(m - nm);
        float ex = __expf(p - nm);
        d = d * sc + ex;
        acc_lo = acc_lo * sc + ex * v_lo;
        acc_hi = acc_hi * sc + ex * v_hi;
        m = nm;
    }

    float inv = d > 0.f ? 1.f / d : 0.f;
    out[(size_t)w * F2DIM + lane] = acc_lo * inv;
    if (hi) out[(size_t)w * F2DIM + 32 + lane] = acc_hi * inv;
}

// ---------------- launch ----------------------------------------------------
extern "C" void kernel_launch(void* const* d_in, const int* in_sizes, int n_in,
                              void* d_out, int out_size) {
    const float* x     = (const float*)d_in[0];
    const int*   src   = (const int*)d_in[1];
    const int*   dst   = (const int*)d_in[2];
    const float* W1    = (const float*)d_in[3];
    const float* attn1 = (const float*)d_in[4];
    const float* W2    = (const float*)d_in[5];
    const float* attn2 = (const float*)d_in[6];
    float* out = (float*)d_out;

    // CSR by destination (recomputed every call; deterministic structure)
    zero_counts_kernel<<<(NN + 255) / 256, 256>>>();
    hist_kernel<<<(EE + 255) / 256, 256>>>(dst);
    scan_kernel<<<1, 1024>>>();
    fill_kernel<<<(EE + 255) / 256, 256>>>(src, dst);

    // layer 1  (NN*32 threads exactly: 50000*32/256 = 6250 blocks)
    gemm1_kernel<<<dim3((NN + 127) / 128, 2), 256>>>(x, W1);
    agg1_kernel<<<(NN * 32) / 256, 256>>>(attn1);

    // layer 2
    gemm2_kernel<<<(NN + 3) / 4, dim3(64, 4)>>>(W2);
    agg2_kernel<<<(NN * 32) / 256, 256>>>(attn2, out);
}

// round 5
// speedup vs baseline: 1.2596x; 1.2596x over previous
#include <cuda_runtime.h>
#include <cuda_bf16.h>
#include <math_constants.h>
#include <cstdint>

#define NN 50000
#define EE 800000
#define FDIM 256        // layer-1 feature dim (4 heads * 64)
#define F2DIM 40        // layer-2 feature dim (1 head * 40)
#define NEG_SLOPE 0.2f
#define SCAN_B 512
#define NBLK ((NN + SCAN_B - 1) / SCAN_B)   // 98

// ---------------- scratch (static device globals; no runtime allocation) ----
__device__ __align__(16) float g_feat1[NN * FDIM];   // x @ W1 ; front reused for feat2
__device__ __align__(16) float g_h2[NN * FDIM];      // elu(layer-1 out), flattened
__device__ int g_colidx[EE];
__device__ int g_counts[NN];
__device__ int g_rowptr[NN + 1];
__device__ int g_cursor[NN];
__device__ int g_bsum[NBLK];
#define G_FEAT2 g_feat1   // feat2[N,40] aliases g_feat1 (dead after agg1)

// ---------------- CSR build ------------------------------------------------
__global__ void zero_counts_kernel() {
    int i = blockIdx.x * blockDim.x + threadIdx.x;
    if (i < NN) g_counts[i] = 0;
}

__global__ void hist_kernel(const int* __restrict__ dst) {
    int e = blockIdx.x * blockDim.x + threadIdx.x;
    if (e < EE) atomicAdd(&g_counts[dst[e]], 1);
}

// phase A: per-block exclusive scan (local) + block sums
__global__ __launch_bounds__(SCAN_B) void scanA_kernel() {
    __shared__ int sh[SCAN_B];
    int i = blockIdx.x * SCAN_B + threadIdx.x;
    int v = (i < NN) ? g_counts[i] : 0;
    sh[threadIdx.x] = v;
    __syncthreads();
    #pragma unroll
    for (int off = 1; off < SCAN_B; off <<= 1) {
        int t = (threadIdx.x >= off) ? sh[threadIdx.x - off] : 0;
        __syncthreads();
        sh[threadIdx.x] += t;
        __syncthreads();
    }
    if (i < NN) g_rowptr[i] = sh[threadIdx.x] - v;       // local exclusive
    if (threadIdx.x == SCAN_B - 1) g_bsum[blockIdx.x] = sh[SCAN_B - 1];
}

// phase B: serial exclusive scan of 98 block sums (tiny)
__global__ void scanB_kernel() {
    if (threadIdx.x == 0) {
        int acc = 0;
        for (int b = 0; b < NBLK; b++) { int t = g_bsum[b]; g_bsum[b] = acc; acc += t; }
    }
}

// phase C: add block offsets
__global__ void scanC_kernel() {
    int i = blockIdx.x * blockDim.x + threadIdx.x;
    if (i < NN) {
        int r = g_rowptr[i] + g_bsum[i / SCAN_B];
        g_rowptr[i] = r;
        g_cursor[i] = r;
    }
    if (i == 0) g_rowptr[NN] = EE;
}

__global__ void fill_kernel(const int* __restrict__ src, const int* __restrict__ dst) {
    int e = blockIdx.x * blockDim.x + threadIdx.x;
    if (e < EE) {
        int p = atomicAdd(&g_cursor[dst[e]], 1);
        g_colidx[p] = src[e];
    }
}

// ---------------- GEMM1 (tensor cores, tf32 2-term split) -------------------
// feat1[N,256] = x[N,256] @ W1[256,256]
// block 128x128, BK=32, 8 warps (2 M x 4 N), warp tile 64x32, mma m16n8k8.
__device__ __forceinline__ void tf32split(float x, uint32_t& hi, uint32_t& lo) {
    asm("cvt.rna.tf32.f32 %0, %1;" : "=r"(hi) : "f"(x));
    float r = x - __uint_as_float(hi);
    asm("cvt.rna.tf32.f32 %0, %1;" : "=r"(lo) : "f"(r));
}

__device__ __forceinline__ void mma_tf32(float* c, const uint32_t* a, const uint32_t* b) {
    asm volatile(
        "mma.sync.aligned.m16n8k8.row.col.f32.tf32.tf32.f32 "
        "{%0,%1,%2,%3}, {%4,%5,%6,%7}, {%8,%9}, {%0,%1,%2,%3};"
        : "+f"(c[0]), "+f"(c[1]), "+f"(c[2]), "+f"(c[3])
        : "r"(a[0]), "r"(a[1]), "r"(a[2]), "r"(a[3]), "r"(b[0]), "r"(b[1]));
}

__global__ __launch_bounds__(256) void gemm1_tc_kernel(const float* __restrict__ A,
                                                       const float* __restrict__ B) {
    __shared__ float As[32][136];   // [k][m], pad 136 -> conflict-free frag loads
    __shared__ float Bs[32][136];   // [k][n]
    int tid = threadIdx.x;
    int lane = tid & 31, wid = tid >> 5;
    int g = lane >> 2, t4 = lane & 3;
    int row0 = blockIdx.x * 128, col0 = blockIdx.y * 128;
    int wm = (wid & 1) * 64, wn = (wid >> 1) * 32;

    float c[4][4][4];
    #pragma unroll
    for (int mt = 0; mt < 4; mt++)
        #pragma unroll
        for (int nt = 0; nt < 4; nt++)
            #pragma unroll
            for (int q = 0; q < 4; q++) c[mt][nt][q] = 0.f;

    int am = tid >> 1;              // 0..127
    int akh = (tid & 1) * 16;       // k half
    int bkr = tid >> 5;             // 0..7
    int bnc = (lane) * 4;           // 0..124

    for (int k0 = 0; k0 < FDIM; k0 += 32) {
        // A tile -> As[k][m] (transposed)
        #pragma unroll
        for (int q = 0; q < 4; q++) {
            int kk = akh + q * 4;
            float4 v = make_float4(0.f, 0.f, 0.f, 0.f);
            int r = row0 + am;
            if (r < NN) v = *(const float4*)&A[(size_t)r * FDIM + k0 + kk];
            As[kk + 0][am] = v.x;
            As[kk + 1][am] = v.y;
            As[kk + 2][am] = v.z;
            As[kk + 3][am] = v.w;
        }
        // B tile -> Bs[k][n]
        #pragma unroll
        for (int q = 0; q < 4; q++) {
            float4 v = *(const float4*)&B[(size_t)(k0 + bkr + q * 8) * 256 + col0 + bnc];
            *(float4*)&Bs[bkr + q * 8][bnc] = v;
        }
        __syncthreads();

        #pragma unroll
        for (int ks = 0; ks < 4; ks++) {
            int kb = ks * 8;
            uint32_t ahi[4][4], alo[4][4];
            #pragma unroll
            for (int mt = 0; mt < 4; mt++) {
                int mr = wm + mt * 16;
                float a0 = As[kb + t4][mr + g];
                float a1 = As[kb + t4][mr + g + 8];
                float a2 = As[kb + t4 + 4][mr + g];
                float a3 = As[kb + t4 + 4][mr + g + 8];
                tf32split(a0, ahi[mt][0], alo[mt][0]);
                tf32split(a1, ahi[mt][1], alo[mt][1]);
                tf32split(a2, ahi[mt][2], alo[mt][2]);
                tf32split(a3, ahi[mt][3], alo[mt][3]);
            }
            uint32_t bhi[4][2], blo[4][2];
            #pragma unroll
            for (int nt = 0; nt < 4; nt++) {
                int nc = wn + nt * 8 + g;
                float b0 = Bs[kb + t4][nc];
                float b1 = Bs[kb + t4 + 4][nc];
                tf32split(b0, bhi[nt][0], blo[nt][0]);
                tf32split(b1, bhi[nt][1], blo[nt][1]);
            }
            #pragma unroll
            for (int mt = 0; mt < 4; mt++)
                #pragma unroll
                for (int nt = 0; nt < 4; nt++) {
                    mma_tf32(c[mt][nt], ahi[mt], bhi[nt]);
                    mma_tf32(c[mt][nt], ahi[mt], blo[nt]);
                    mma_tf32(c[mt][nt], alo[mt], bhi[nt]);
                }
        }
        __syncthreads();
    }

    // epilogue: c0,c1 -> (row g, cols 2t4,2t4+1); c2,c3 -> row g+8
    #pragma unroll
    for (int mt = 0; mt < 4; mt++) {
        int r = row0 + wm + mt * 16 + g;
        #pragma unroll
        for (int nt = 0; nt < 4; nt++) {
            int cc = col0 + wn + nt * 8 + 2 * t4;
            if (r < NN)
                *(float2*)&g_feat1[(size_t)r * FDIM + cc] = make_float2(c[mt][nt][0], c[mt][nt][1]);
            if (r + 8 < NN)
                *(float2*)&g_feat1[(size_t)(r + 8) * FDIM + cc] = make_float2(c[mt][nt][2], c[mt][nt][3]);
        }
    }
}

// ---------------- layer-1 fused edge-softmax + aggregate --------------------
__device__ __forceinline__ float4 leaky4(float4 v) {
    float4 r;
    r.x = v.x > 0.f ? v.x : NEG_SLOPE * v.x;
    r.y = v.y > 0.f ? v.y : NEG_SLOPE * v.y;
    r.z = v.z > 0.f ? v.z : NEG_SLOPE * v.z;
    r.w = v.w > 0.f ? v.w : NEG_SLOPE * v.w;
    return r;
}
__device__ __forceinline__ float eluf(float x) { return x > 0.f ? x : expm1f(x); }

__device__ __forceinline__ float dot4(float4 a, float4 b) {
    return a.x * b.x + a.y * b.y + a.z * b.z + a.w * b.w;
}
__device__ __forceinline__ float4 add4(float4 a, float4 b) {
    return make_float4(a.x + b.x, a.y + b.y, a.z + b.z, a.w + b.w);
}

__global__ __launch_bounds__(256) void agg1_kernel(const float* __restrict__ attn) {
    int w = (blockIdx.x * blockDim.x + threadIdx.x) >> 5;   // always < NN by grid sizing
    int lane = threadIdx.x & 31;

    const float4* feat = (const float4*)g_feat1;   // 64 float4 per row
    const float4* at4  = (const float4*)attn;

    float4 aA = at4[lane];
    float4 aB = at4[32 + lane];
    float4 fd0 = feat[(size_t)w * 64 + lane];
    float4 fd1 = feat[(size_t)w * 64 + 32 + lane];

    int beg = g_rowptr[w], end = g_rowptr[w + 1];
    float mA = -CUDART_INF_F, mB = -CUDART_INF_F, dA = 0.f, dB = 0.f;
    float4 acc0 = make_float4(0.f, 0.f, 0.f, 0.f);
    float4 acc1 = make_float4(0.f, 0.f, 0.f, 0.f);

    int k = beg;
    // two edges per iteration: 4 independent shuffle chains hide SHFL latency
    for (; k + 1 < end; k += 2) {
        int sa = g_colidx[k];
        int sb = g_colidx[k + 1];
        float4 va0 = feat[(size_t)sa * 64 + lane];
        float4 va1 = feat[(size_t)sa * 64 + 32 + lane];
        float4 vb0 = feat[(size_t)sb * 64 + lane];
        float4 vb1 = feat[(size_t)sb * 64 + 32 + lane];
        float pa0 = dot4(leaky4(add4(va0, fd0)), aA);
        float pa1 = dot4(leaky4(add4(va1, fd1)), aB);
        float pb0 = dot4(leaky4(add4(vb0, fd0)), aA);
        float pb1 = dot4(leaky4(add4(vb1, fd1)), aB);
        #pragma unroll
        for (int off = 8; off > 0; off >>= 1) {
            pa0 += __shfl_xor_sync(0xffffffffu, pa0, off);
            pa1 += __shfl_xor_sync(0xffffffffu, pa1, off);
            pb0 += __shfl_xor_sync(0xffffffffu, pb0, off);
            pb1 += __shfl_xor_sync(0xffffffffu, pb1, off);
        }
        // edge a
        {
            float nmA = fmaxf(mA, pa0), nmB = fmaxf(mB, pa1);
            float scA = __expf(mA - nmA), exA = __expf(pa0 - nmA);
            float scB = __expf(mB - nmB), exB = __expf(pa1 - nmB);
            dA = dA * scA + exA;
            dB = dB * scB + exB;
            acc0.x = acc0.x * scA + exA * va0.x; acc0.y = acc0.y * scA + exA * va0.y;
            acc0.z = acc0.z * scA + exA * va0.z; acc0.w = acc0.w * scA + exA * va0.w;
            acc1.x = acc1.x * scB + exB * va1.x; acc1.y = acc1.y * scB + exB * va1.y;
            acc1.z = acc1.z * scB + exB * va1.z; acc1.w = acc1.w * scB + exB * va1.w;
            mA = nmA; mB = nmB;
        }
        // edge b
        {
            float nmA = fmaxf(mA, pb0), nmB = fmaxf(mB, pb1);
            float scA = __expf(mA - nmA), exA = __expf(pb0 - nmA);
            float scB = __expf(mB - nmB), exB = __expf(pb1 - nmB);
            dA = dA * scA + exA;
            dB = dB * scB + exB;
            acc0.x = acc0.x * scA + exA * vb0.x; acc0.y = acc0.y * scA + exA * vb0.y;
            acc0.z = acc0.z * scA + exA * vb0.z; acc0.w = acc0.w * scA + exA * vb0.w;
            acc1.x = acc1.x * scB + exB * vb1.x; acc1.y = acc1.y * scB + exB * vb1.y;
            acc1.z = acc1.z * scB + exB * vb1.z; acc1.w = acc1.w * scB + exB * vb1.w;
            mA = nmA; mB = nmB;
        }
    }
    if (k < end) {   // tail edge
        int s = g_colidx[k];
        float4 v0 = feat[(size_t)s * 64 + lane];
        float4 v1 = feat[(size_t)s * 64 + 32 + lane];
        float p0 = dot4(leaky4(add4(v0, fd0)), aA);
        float p1 = dot4(leaky4(add4(v1, fd1)), aB);
        #pragma unroll
        for (int off = 8; off > 0; off >>= 1) {
            p0 += __shfl_xor_sync(0xffffffffu, p0, off);
            p1 += __shfl_xor_sync(0xffffffffu, p1, off);
        }
        float nmA = fmaxf(mA, p0), nmB = fmaxf(mB, p1);
        float scA = __expf(mA - nmA), exA = __expf(p0 - nmA);
        float scB = __expf(mB - nmB), exB = __expf(p1 - nmB);
        dA = dA * scA + exA;
        dB = dB * scB + exB;
        acc0.x = acc0.x * scA + exA * v0.x; acc0.y = acc0.y * scA + exA * v0.y;
        acc0.z = acc0.z * scA + exA * v0.z; acc0.w = acc0.w * scA + exA * v0.w;
        acc1.x = acc1.x * scB + exB * v1.x; acc1.y = acc1.y * scB + exB * v1.y;
        acc1.z = acc1.z * scB + exB * v1.z; acc1.w = acc1.w * scB + exB * v1.w;
    }

    float iA = dA > 0.f ? 1.f / dA : 0.f;
    float iB = dB > 0.f ? 1.f / dB : 0.f;
    float4 o0 = make_float4(eluf(acc0.x * iA), eluf(acc0.y * iA), eluf(acc0.z * iA), eluf(acc0.w * iA));
    float4 o1 = make_float4(eluf(acc1.x * iB), eluf(acc1.y * iB), eluf(acc1.z * iB), eluf(acc1.w * iB));
    float4* out = (float4*)g_h2;
    out[(size_t)w * 64 + lane] = o0;
    out[(size_t)w * 64 + 32 + lane] = o1;
}

// ---------------- GEMM2: feat2[N,40] = h2[N,256] @ W2[256,40] ---------------
__global__ __launch_bounds__(256) void gemm2_kernel(const float* __restrict__ W2) {
    __shared__ float hs[4][256];
    int n0 = blockIdx.x * 4;
    int tid = threadIdx.y * 64 + threadIdx.x;
    for (int i = tid; i < 1024; i += 256) {
        int r = n0 + (i >> 8);
        hs[i >> 8][i & 255] = (r < NN) ? g_h2[(size_t)r * 256 + (i & 255)] : 0.f;
    }
    __syncthreads();
    int c = threadIdx.x;
    int r = n0 + threadIdx.y;
    if (c < F2DIM && r < NN) {
        float s = 0.f;
        #pragma unroll 8
        for (int k = 0; k < 256; k++) s += hs[threadIdx.y][k] * W2[k * F2DIM + c];
        G_FEAT2[(size_t)r * F2DIM + c] = s;
    }
}

// ---------------- layer-2 fused edge-softmax + aggregate --------------------
__global__ __launch_bounds__(256) void agg2_kernel(const float* __restrict__ attn2,
                                                   float* __restrict__ out) {
    int w = (blockIdx.x * blockDim.x + threadIdx.x) >> 5;
    int lane = threadIdx.x & 31;

    bool hi = lane < 8;
    float a_lo = attn2[lane];
    float a_hi = hi ? attn2[32 + lane] : 0.f;
    float fd_lo = G_FEAT2[(size_t)w * F2DIM + lane];
    float fd_hi = hi ? G_FEAT2[(size_t)w * F2DIM + 32 + lane] : 0.f;

    int beg = g_rowptr[w], end = g_rowptr[w + 1];
    float m = -CUDART_INF_F, d = 0.f, acc_lo = 0.f, acc_hi = 0.f;

    for (int k = beg; k < end; k++) {
        int s = g_colidx[k];
        float v_lo = G_FEAT2[(size_t)s * F2DIM + lane];
        float v_hi = hi ? G_FEAT2[(size_t)s * F2DIM + 32 + lane] : 0.f;
        float e_lo = v_lo + fd_lo; e_lo = e_lo > 0.f ? e_lo : NEG_SLOPE * e_lo;
        float e_hi = v_hi + fd_hi; e_hi = e_hi > 0.f ? e_hi : NEG_SLOPE * e_hi;
        float p = e_lo * a_lo + e_hi * a_hi;
        #pragma unroll
        for (int off = 16; off > 0; off >>= 1) p += __shfl_xor_sync(0xffffffffu, p, off);
        float nm = fmaxf(m, p);
        float sc = __expf(m - nm);
        float ex = __expf(p - nm);
        d = d * sc + ex;
        acc_lo = acc_lo * sc + ex * v_lo;
        acc_hi = acc_hi * sc + ex * v_hi;
        m = nm;
    }

    float inv = d > 0.f ? 1.f / d : 0.f;
    out[(size_t)w * F2DIM + lane] = acc_lo * inv;
    if (hi) out[(size_t)w * F2DIM + 32 + lane] = acc_hi * inv;
}

// ---------------- launch ----------------------------------------------------
extern "C" void kernel_launch(void* const* d_in, const int* in_sizes, int n_in,
                              void* d_out, int out_size) {
    const float* x     = (const float*)d_in[0];
    const int*   src   = (const int*)d_in[1];
    const int*   dst   = (const int*)d_in[2];
    const float* W1    = (const float*)d_in[3];
    const float* attn1 = (const float*)d_in[4];
    const float* W2    = (const float*)d_in[5];
    const float* attn2 = (const float*)d_in[6];
    float* out = (float*)d_out;

    // CSR by destination
    zero_counts_kernel<<<(NN + 255) / 256, 256>>>();
    hist_kernel<<<(EE + 255) / 256, 256>>>(dst);
    scanA_kernel<<<NBLK, SCAN_B>>>();
    scanB_kernel<<<1, 32>>>();
    scanC_kernel<<<(NN + 255) / 256, 256>>>();
    fill_kernel<<<(EE + 255) / 256, 256>>>(src, dst);

    // layer 1
    gemm1_tc_kernel<<<dim3((NN + 127) / 128, 2), 256>>>(x, W1);
    agg1_kernel<<<(NN * 32) / 256, 256>>>(attn1);

    // layer 2
    gemm2_kernel<<<(NN + 3) / 4, dim3(64, 4)>>>(W2);
    agg2_kernel<<<(NN * 32) / 256, 256>>>(attn2, out);
}